// round 1
// baseline (speedup 1.0000x reference)
#include <cuda_runtime.h>

#define F_N   65536
#define LP_N  8
#define NL_N  8192
#define DG_N  64
#define D_N   32
#define IT_N  8

// ---------------- scratch (static device globals; no allocation) -----------
__device__ float g_path_state[F_N * D_N];        //  8 MB
__device__ float g_link_state[NL_N * D_N];       //  1 MB
__device__ float g_pss[F_N * 9 * D_N];           // 75.5 MB  [F][9][32]
__device__ float g_MX [NL_N * 96];               //  3 MB  link_state @ pg_w + pg_b[0]
__device__ float g_MHL[NL_N * 96];               //  3 MB  link_state @ lg_u + lg_b[1]

// ---------------- activations ---------------------------------------------
__device__ __forceinline__ float sig_(float x)  { return __fdividef(1.f, 1.f + __expf(-x)); }
__device__ __forceinline__ float tanh_(float x) { return __fdividef(2.f, 1.f + __expf(-2.f * x)) - 1.f; }
__device__ __forceinline__ float selu_(float x) {
    return x > 0.f ? 1.0507009873554805f * x
                   : 1.7580993408473766f * (__expf(x) - 1.f);
}
__device__ __forceinline__ float softplus_(float x) {
    if (x > 15.f) return x;
    return __logf(1.f + __expf(x));
}

// ---------------- init: flow encoder (warp per flow) -----------------------
__global__ __launch_bounds__(256) void flow_init_kernel(
    const float* __restrict__ tr, const float* __restrict__ ln,
    const float* __restrict__ lo, const float* __restrict__ pd,
    const float* __restrict__ w1, const float* __restrict__ b1,
    const float* __restrict__ w2, const float* __restrict__ b2)
{
    int lane = threadIdx.x & 31;
    int f    = (blockIdx.x * 256 + threadIdx.x) >> 5;
    float x0 = (tr[f] - 0.5f) * 2.f;
    float x1 = (ln[f] - 0.5f) * 2.f;
    float x2 = (lo[f] - 0.1f) * 5.f;
    float x3 = (pd[f] - 0.2f) * 3.f;
    float h1 = b1[lane] + x0 * w1[lane] + x1 * w1[32 + lane]
                        + x2 * w1[64 + lane] + x3 * w1[96 + lane];
    h1 = selu_(h1);
    float o = b2[lane];
#pragma unroll
    for (int k = 0; k < 32; k++)
        o += __shfl_sync(0xffffffffu, h1, k) * w2[k * 32 + lane];
    g_path_state[f * 32 + lane] = selu_(o);
}

// ---------------- init: link encoder + MX/MHL (warp per link) --------------
__global__ __launch_bounds__(256) void link_init_kernel(
    const float* __restrict__ tr, const float* __restrict__ cap,
    const int*   __restrict__ f2lf,
    const float* __restrict__ w1, const float* __restrict__ b1,
    const float* __restrict__ w2, const float* __restrict__ b2,
    const float* __restrict__ pg_w, const float* __restrict__ pg_b,
    const float* __restrict__ lg_u, const float* __restrict__ lg_b)
{
    int lane = threadIdx.x & 31;
    int l    = (blockIdx.x * 256 + threadIdx.x) >> 5;
    float s = tr[f2lf[l * 64 + lane]] + tr[f2lf[l * 64 + 32 + lane]];
#pragma unroll
    for (int o = 16; o; o >>= 1) s += __shfl_xor_sync(0xffffffffu, s, o);
    float c    = cap[l];
    float load = __fdividef(s * (1.f / 64.f), c);
    float x0 = (c - 1.f);
    float h1 = selu_(b1[lane] + x0 * w1[lane] + load * w1[32 + lane]);
    float o2 = b2[lane];
#pragma unroll
    for (int k = 0; k < 32; k++)
        o2 += __shfl_sync(0xffffffffu, h1, k) * w2[k * 32 + lane];
    float ls = selu_(o2);
    g_link_state[l * 32 + lane] = ls;

    // MX = ls @ pg_w + pg_b[0] ; MHL = ls @ lg_u + lg_b[1]
    float m0 = pg_b[lane], m1 = pg_b[32 + lane], m2 = pg_b[64 + lane];
    float n0 = lg_b[96 + lane], n1 = lg_b[128 + lane], n2 = lg_b[160 + lane];
#pragma unroll
    for (int k = 0; k < 32; k++) {
        float hk = __shfl_sync(0xffffffffu, ls, k);
        m0 += hk * pg_w[k * 96 + lane];
        m1 += hk * pg_w[k * 96 + 32 + lane];
        m2 += hk * pg_w[k * 96 + 64 + lane];
        n0 += hk * lg_u[k * 96 + lane];
        n1 += hk * lg_u[k * 96 + 32 + lane];
        n2 += hk * lg_u[k * 96 + 64 + lane];
    }
    g_MX [l * 96 + lane] = m0; g_MX [l * 96 + 32 + lane] = m1; g_MX [l * 96 + 64 + lane] = m2;
    g_MHL[l * 96 + lane] = n0; g_MHL[l * 96 + 32 + lane] = n1; g_MHL[l * 96 + 64 + lane] = n2;
}

// ---------------- path GRU scan (warp per flow) ----------------------------
__global__ __launch_bounds__(256) void path_kernel(
    const int* __restrict__ l2f,
    const float* __restrict__ pg_u, const float* __restrict__ pg_b)
{
    __shared__ __align__(16) float Us[3072];   // pg_u [32][96]
    __shared__ float Bs[96];                   // recurrent bias pg_b[1]
    int tid = threadIdx.x;
    for (int i = tid; i < 3072; i += 256) Us[i] = pg_u[i];
    if (tid < 96) Bs[tid] = pg_b[96 + tid];
    __syncthreads();

    int lane = tid & 31;
    int f    = (blockIdx.x * 256 + tid) >> 5;
    float h  = g_path_state[f * 32 + lane];
    float* pssf = g_pss + f * 288;
    pssf[lane] = h;                            // prev at slot 0
    const int* lrow = l2f + f * 8;

#pragma unroll 1
    for (int s = 0; s < 8; s++) {
        int l = __ldg(lrow + s);
        const float* mx = g_MX + l * 96;
        float xz = __ldg(mx + lane), xr = __ldg(mx + 32 + lane), xh = __ldg(mx + 64 + lane);
        float az = Bs[lane], ar = Bs[32 + lane], ah = Bs[64 + lane];
#pragma unroll
        for (int k = 0; k < 32; k++) {
            float hk = __shfl_sync(0xffffffffu, h, k);
            az += hk * Us[k * 96 + lane];
            ar += hk * Us[k * 96 + 32 + lane];
            ah += hk * Us[k * 96 + 64 + lane];
        }
        float z  = sig_(xz + az);
        float rr = sig_(xr + ar);
        float c  = tanh_(xh + rr * ah);
        h = z * h + (1.f - z) * c;
        pssf[(s + 1) * 32 + lane] = h;
    }
    g_path_state[f * 32 + lane] = h;
}

// ---------------- link attention + link GRU (+MX/MHL refresh) --------------
// block = 128 threads (4 warps), 4 links per block processed sequentially
__global__ __launch_bounds__(128) void link_kernel(
    const int* __restrict__ f2lf, const int* __restrict__ f2lp,
    const float* __restrict__ att_w, const float* __restrict__ att_b,
    const float* __restrict__ lg_w,  const float* __restrict__ lg_b,
    const float* __restrict__ pg_w,  const float* __restrict__ pg_b,
    const float* __restrict__ lg_u)
{
    __shared__ __align__(16) float AW[1024];   // att_w [32][32]
    __shared__ __align__(16) float LW[3072];   // lg_w  [32][96]
    __shared__ float red[4][32];
    int tid = threadIdx.x, lane = tid & 31, w = tid >> 5;
    for (int i = tid; i < 1024; i += 128) AW[i] = att_w[i];
    for (int i = tid; i < 3072; i += 128) LW[i] = lg_w[i];
    __syncthreads();

    for (int li = 0; li < 4; li++) {
        int l = blockIdx.x * 4 + li;
        float aggd = 0.f;
        for (int gi = 0; gi < 16; gi++) {
            int g   = w * 16 + gi;
            int fl  = __ldg(f2lf + l * 64 + g);
            int pos = __ldg(f2lp + l * 64 + g);
            float pg = g_pss[(fl * 9 + pos) * 32 + lane];   // coalesced 128B row
            float a = att_b[lane];
#pragma unroll
            for (int k = 0; k < 32; k++)
                a += __shfl_sync(0xffffffffu, pg, k) * AW[k * 32 + lane];
            a = (a > 0.f) ? a : 0.2f * a;                   // leaky_relu(0.2)
            // softmax over the 32 channels (lanes)
            float m = a;
#pragma unroll
            for (int o = 16; o; o >>= 1) m = fmaxf(m, __shfl_xor_sync(0xffffffffu, m, o));
            float e  = __expf(a - m);
            float se = e;
#pragma unroll
            for (int o = 16; o; o >>= 1) se += __shfl_xor_sync(0xffffffffu, se, o);
            aggd += __fdividef(e, se) * pg;
        }
        red[w][lane] = aggd;
        __syncthreads();
        if (w == 0) {
            float agg = red[0][lane] + red[1][lane] + red[2][lane] + red[3][lane];
            // link GRU: mx = agg @ lg_w + lg_b[0] ; mh = MHL (precomputed)
            float az = lg_b[lane], ar = lg_b[32 + lane], ah = lg_b[64 + lane];
#pragma unroll
            for (int k = 0; k < 32; k++) {
                float ak = __shfl_sync(0xffffffffu, agg, k);
                az += ak * LW[k * 96 + lane];
                ar += ak * LW[k * 96 + 32 + lane];
                ah += ak * LW[k * 96 + 64 + lane];
            }
            const float* mh = g_MHL + l * 96;
            float hz = mh[lane], hr = mh[32 + lane], hh = mh[64 + lane];
            float h = g_link_state[l * 32 + lane];
            float z  = sig_(az + hz);
            float rr = sig_(ar + hr);
            float c  = tanh_(ah + rr * hh);
            h = z * h + (1.f - z) * c;
            g_link_state[l * 32 + lane] = h;
            // refresh MX / MHL for the next iteration
            float m0 = pg_b[lane], m1 = pg_b[32 + lane], m2 = pg_b[64 + lane];
            float n0 = lg_b[96 + lane], n1 = lg_b[128 + lane], n2 = lg_b[160 + lane];
#pragma unroll
            for (int k = 0; k < 32; k++) {
                float hk = __shfl_sync(0xffffffffu, h, k);
                m0 += hk * pg_w[k * 96 + lane];
                m1 += hk * pg_w[k * 96 + 32 + lane];
                m2 += hk * pg_w[k * 96 + 64 + lane];
                n0 += hk * lg_u[k * 96 + lane];
                n1 += hk * lg_u[k * 96 + 32 + lane];
                n2 += hk * lg_u[k * 96 + 64 + lane];
            }
            float* mxp = g_MX + l * 96;
            mxp[lane] = m0; mxp[32 + lane] = m1; mxp[64 + lane] = m2;
            float* mhp = g_MHL + l * 96;
            mhp[lane] = n0; mhp[32 + lane] = n1; mhp[64 + lane] = n2;
        }
        __syncthreads();
    }
}

// ---------------- readout (thread per flow) --------------------------------
__global__ __launch_bounds__(128) void readout_kernel(
    const float* __restrict__ pdly, const float* __restrict__ cap,
    const int*   __restrict__ l2f,
    const float* __restrict__ w1, const float* __restrict__ b1,
    const float* __restrict__ w2, const float* __restrict__ b2,
    const float* __restrict__ w3, const float* __restrict__ b3,
    float* __restrict__ out)
{
    __shared__ __align__(16) float W1[512];
    __shared__ __align__(16) float W2[128];
    __shared__ float B1[16], B2[8], W3s[8];
    int tid = threadIdx.x;
    for (int i = tid; i < 512; i += 128) W1[i] = w1[i];
    if (tid < 128) W2[tid] = w2[tid];
    if (tid < 16)  B1[tid] = b1[tid];
    if (tid < 8) { B2[tid] = b2[tid]; W3s[tid] = w3[tid]; }
    __syncthreads();

    int f = blockIdx.x * 128 + tid;
    float b3v = __ldg(b3);
    float acc = 0.f;
#pragma unroll 1
    for (int s = 1; s <= 8; s++) {
        float r[32];
        const float4* row = (const float4*)(g_pss + (f * 9 + s) * 32);
#pragma unroll
        for (int i = 0; i < 8; i++) {
            float4 v = row[i];
            r[4 * i] = v.x; r[4 * i + 1] = v.y; r[4 * i + 2] = v.z; r[4 * i + 3] = v.w;
        }
        float h1[16];
#pragma unroll
        for (int j = 0; j < 16; j++) h1[j] = B1[j];
#pragma unroll
        for (int k = 0; k < 32; k++) {
            float rk = r[k];
            const float4* wr = (const float4*)(W1 + k * 16);
#pragma unroll
            for (int q = 0; q < 4; q++) {
                float4 wv = wr[q];
                h1[4 * q]     += rk * wv.x;
                h1[4 * q + 1] += rk * wv.y;
                h1[4 * q + 2] += rk * wv.z;
                h1[4 * q + 3] += rk * wv.w;
            }
        }
#pragma unroll
        for (int j = 0; j < 16; j++) h1[j] = selu_(h1[j]);
        float h2[8];
#pragma unroll
        for (int j = 0; j < 8; j++) h2[j] = B2[j];
#pragma unroll
        for (int k = 0; k < 16; k++) {
            float rk = h1[k];
            const float4* wr = (const float4*)(W2 + k * 8);
            float4 wa = wr[0], wb = wr[1];
            h2[0] += rk * wa.x; h2[1] += rk * wa.y; h2[2] += rk * wa.z; h2[3] += rk * wa.w;
            h2[4] += rk * wb.x; h2[5] += rk * wb.y; h2[6] += rk * wb.z; h2[7] += rk * wb.w;
        }
        float a = b3v;
#pragma unroll
        for (int k = 0; k < 8; k++) a += selu_(h2[k]) * W3s[k];
        int lidx = __ldg(l2f + f * 8 + (s - 1));
        acc += __fdividef(softplus_(a), __ldg(cap + lidx));
    }
    out[f] = acc + pdly[f];
}

// ---------------- launch ----------------------------------------------------
extern "C" void kernel_launch(void* const* d_in, const int* in_sizes, int n_in,
                              void* d_out, int out_size)
{
    (void)in_sizes; (void)n_in; (void)out_size;
    const float* tr    = (const float*)d_in[0];
    const float* ln    = (const float*)d_in[1];
    const float* lo    = (const float*)d_in[2];
    const float* pdly  = (const float*)d_in[3];
    /* d_in[4] flow_packet_size unused by reference */
    const float* cap   = (const float*)d_in[5];
    const int*   l2f   = (const int*)d_in[6];
    const int*   f2lf  = (const int*)d_in[7];
    const int*   f2lp  = (const int*)d_in[8];
    const float* fe_w1 = (const float*)d_in[9];
    const float* fe_b1 = (const float*)d_in[10];
    const float* fe_w2 = (const float*)d_in[11];
    const float* fe_b2 = (const float*)d_in[12];
    const float* le_w1 = (const float*)d_in[13];
    const float* le_b1 = (const float*)d_in[14];
    const float* le_w2 = (const float*)d_in[15];
    const float* le_b2 = (const float*)d_in[16];
    const float* att_w = (const float*)d_in[17];
    const float* att_b = (const float*)d_in[18];
    const float* pg_w  = (const float*)d_in[19];
    const float* pg_u  = (const float*)d_in[20];
    const float* pg_b  = (const float*)d_in[21];
    const float* lg_w  = (const float*)d_in[22];
    const float* lg_u  = (const float*)d_in[23];
    const float* lg_b  = (const float*)d_in[24];
    const float* ro_w1 = (const float*)d_in[25];
    const float* ro_b1 = (const float*)d_in[26];
    const float* ro_w2 = (const float*)d_in[27];
    const float* ro_b2 = (const float*)d_in[28];
    const float* ro_w3 = (const float*)d_in[29];
    const float* ro_b3 = (const float*)d_in[30];
    float* out = (float*)d_out;

    flow_init_kernel<<<F_N / 8, 256>>>(tr, ln, lo, pdly, fe_w1, fe_b1, fe_w2, fe_b2);
    link_init_kernel<<<NL_N / 8, 256>>>(tr, cap, f2lf, le_w1, le_b1, le_w2, le_b2,
                                        pg_w, pg_b, lg_u, lg_b);
    for (int it = 0; it < IT_N; ++it) {
        path_kernel<<<F_N / 8, 256>>>(l2f, pg_u, pg_b);
        link_kernel<<<NL_N / 4, 128>>>(f2lf, f2lp, att_w, att_b,
                                       lg_w, lg_b, pg_w, pg_b, lg_u);
    }
    readout_kernel<<<F_N / 128, 128>>>(pdly, cap, l2f,
                                       ro_w1, ro_b1, ro_w2, ro_b2, ro_w3, ro_b3, out);
}

// round 3
// speedup vs baseline: 3.2374x; 3.2374x over previous
#include <cuda_runtime.h>

#define F_N   65536
#define LP_N  8
#define NL_N  8192
#define DG_N  64
#define D_N   32
#define IT_N  8

// ---------------- scratch (static device globals; no allocation) -----------
__device__ float g_path_state[F_N * D_N];        //  8 MB
__device__ float g_link_state[NL_N * D_N];       //  1 MB
__device__ float g_pss[F_N * 9 * D_N];           // 75.5 MB  [F][9][32]
__device__ float g_MX [NL_N * 96];               //  3 MB  link_state @ pg_w + pg_b[0]
__device__ float g_MHL[NL_N * 96];               //  3 MB  link_state @ lg_u + lg_b[1]

// ---------------- activations ---------------------------------------------
__device__ __forceinline__ float sig_(float x)  { return __fdividef(1.f, 1.f + __expf(-x)); }
__device__ __forceinline__ float tanh_(float x) { return __fdividef(2.f, 1.f + __expf(-2.f * x)) - 1.f; }
__device__ __forceinline__ float selu_(float x) {
    return x > 0.f ? 1.0507009873554805f * x
                   : 1.7580993408473766f * (__expf(x) - 1.f);
}
__device__ __forceinline__ float softplus_(float x) {
    if (x > 15.f) return x;
    return __logf(1.f + __expf(x));
}

// ---------------- init: flow encoder (warp per flow) -----------------------
__global__ __launch_bounds__(256) void flow_init_kernel(
    const float* __restrict__ tr, const float* __restrict__ ln,
    const float* __restrict__ lo, const float* __restrict__ pd,
    const float* __restrict__ w1, const float* __restrict__ b1,
    const float* __restrict__ w2, const float* __restrict__ b2)
{
    int lane = threadIdx.x & 31;
    int f    = (blockIdx.x * 256 + threadIdx.x) >> 5;
    float x0 = (tr[f] - 0.5f) * 2.f;
    float x1 = (ln[f] - 0.5f) * 2.f;
    float x2 = (lo[f] - 0.1f) * 5.f;
    float x3 = (pd[f] - 0.2f) * 3.f;
    float h1 = b1[lane] + x0 * w1[lane] + x1 * w1[32 + lane]
                        + x2 * w1[64 + lane] + x3 * w1[96 + lane];
    h1 = selu_(h1);
    float o = b2[lane];
#pragma unroll
    for (int k = 0; k < 32; k++)
        o += __shfl_sync(0xffffffffu, h1, k) * w2[k * 32 + lane];
    g_path_state[f * 32 + lane] = selu_(o);
}

// ---------------- init: link encoder + MX/MHL (warp per link) --------------
__global__ __launch_bounds__(256) void link_init_kernel(
    const float* __restrict__ tr, const float* __restrict__ cap,
    const int*   __restrict__ f2lf,
    const float* __restrict__ w1, const float* __restrict__ b1,
    const float* __restrict__ w2, const float* __restrict__ b2,
    const float* __restrict__ pg_w, const float* __restrict__ pg_b,
    const float* __restrict__ lg_u, const float* __restrict__ lg_b)
{
    int lane = threadIdx.x & 31;
    int l    = (blockIdx.x * 256 + threadIdx.x) >> 5;
    float s = tr[f2lf[l * 64 + lane]] + tr[f2lf[l * 64 + 32 + lane]];
#pragma unroll
    for (int o = 16; o; o >>= 1) s += __shfl_xor_sync(0xffffffffu, s, o);
    float c    = cap[l];
    float load = __fdividef(s * (1.f / 64.f), c);
    float x0 = (c - 1.f);
    float h1 = selu_(b1[lane] + x0 * w1[lane] + load * w1[32 + lane]);
    float o2 = b2[lane];
#pragma unroll
    for (int k = 0; k < 32; k++)
        o2 += __shfl_sync(0xffffffffu, h1, k) * w2[k * 32 + lane];
    float ls = selu_(o2);
    g_link_state[l * 32 + lane] = ls;

    // MX = ls @ pg_w + pg_b[0] ; MHL = ls @ lg_u + lg_b[1]
    float m0 = pg_b[lane], m1 = pg_b[32 + lane], m2 = pg_b[64 + lane];
    float n0 = lg_b[96 + lane], n1 = lg_b[128 + lane], n2 = lg_b[160 + lane];
#pragma unroll
    for (int k = 0; k < 32; k++) {
        float hk = __shfl_sync(0xffffffffu, ls, k);
        m0 += hk * pg_w[k * 96 + lane];
        m1 += hk * pg_w[k * 96 + 32 + lane];
        m2 += hk * pg_w[k * 96 + 64 + lane];
        n0 += hk * lg_u[k * 96 + lane];
        n1 += hk * lg_u[k * 96 + 32 + lane];
        n2 += hk * lg_u[k * 96 + 64 + lane];
    }
    g_MX [l * 96 + lane] = m0; g_MX [l * 96 + 32 + lane] = m1; g_MX [l * 96 + 64 + lane] = m2;
    g_MHL[l * 96 + lane] = n0; g_MHL[l * 96 + 32 + lane] = n1; g_MHL[l * 96 + 64 + lane] = n2;
}

// ---------------- path GRU scan: persistent, register-resident U -----------
// warp per flow (grid-stride). Lane owns output channel; pg_u columns live in
// registers (96 regs) loaded once per warp.
__global__ __launch_bounds__(256) void path_kernel(
    const int* __restrict__ l2f,
    const float* __restrict__ pg_u, const float* __restrict__ pg_b)
{
    int lane = threadIdx.x & 31;
    float uz[32], ur[32], uh[32];
#pragma unroll
    for (int k = 0; k < 32; k++) {
        uz[k] = __ldg(pg_u + k * 96 + lane);
        ur[k] = __ldg(pg_u + k * 96 + 32 + lane);
        uh[k] = __ldg(pg_u + k * 96 + 64 + lane);
    }
    float bz = __ldg(pg_b + 96 + lane);
    float br = __ldg(pg_b + 128 + lane);
    float bh = __ldg(pg_b + 160 + lane);

    int warps_total = gridDim.x * (blockDim.x >> 5);
    int wid = blockIdx.x * (blockDim.x >> 5) + (threadIdx.x >> 5);

    for (int f = wid; f < F_N; f += warps_total) {
        float h = g_path_state[f * 32 + lane];
        float* pssf = g_pss + f * 288;
        pssf[lane] = h;
        const int* lrow = l2f + f * 8;

        int l = __ldg(lrow);
        const float* mx = g_MX + l * 96;
        float xz = __ldg(mx + lane), xr = __ldg(mx + 32 + lane), xh = __ldg(mx + 64 + lane);

#pragma unroll 1
        for (int s = 0; s < 8; s++) {
            float xzn = 0.f, xrn = 0.f, xhn = 0.f;
            if (s < 7) {                       // prefetch next step's MX row
                int ln2 = __ldg(lrow + s + 1);
                const float* mxn = g_MX + ln2 * 96;
                xzn = __ldg(mxn + lane); xrn = __ldg(mxn + 32 + lane); xhn = __ldg(mxn + 64 + lane);
            }
            float az = bz, ar = br, ah = bh;
#pragma unroll
            for (int k = 0; k < 32; k++) {
                float hk = __shfl_sync(0xffffffffu, h, k);
                az = fmaf(hk, uz[k], az);
                ar = fmaf(hk, ur[k], ar);
                ah = fmaf(hk, uh[k], ah);
            }
            float z  = sig_(xz + az);
            float rr = sig_(xr + ar);
            float c  = tanh_(xh + rr * ah);
            h = z * h + (1.f - z) * c;
            pssf[(s + 1) * 32 + lane] = h;
            xz = xzn; xr = xrn; xh = xhn;
        }
        g_path_state[f * 32 + lane] = h;
    }
}

// ---------------- link attention + GRU: warp per link ----------------------
// att_w column register-resident; 4-way batched gathers; no inter-warp sync.
__global__ __launch_bounds__(256) void link_kernel(
    const int* __restrict__ f2lf, const int* __restrict__ f2lp,
    const float* __restrict__ att_w, const float* __restrict__ att_b,
    const float* __restrict__ lg_w,  const float* __restrict__ lg_b,
    const float* __restrict__ pg_w,  const float* __restrict__ pg_b,
    const float* __restrict__ lg_u)
{
    __shared__ __align__(16) float LW[3072];   // lg_w  [32][96]
    __shared__ __align__(16) float PW[3072];   // pg_w  [32][96]
    __shared__ __align__(16) float LU[3072];   // lg_u  [32][96]
    int tid = threadIdx.x, lane = tid & 31, w = tid >> 5;
    for (int i = tid; i < 3072; i += 256) {
        LW[i] = lg_w[i]; PW[i] = pg_w[i]; LU[i] = lg_u[i];
    }
    __syncthreads();

    int l = blockIdx.x * 8 + w;

    // register-resident att_w column for this lane
    float awr[32];
#pragma unroll
    for (int k = 0; k < 32; k++) awr[k] = __ldg(att_w + k * 32 + lane);
    float ab = __ldg(att_b + lane);

    // preload gather indices: lane g and g+32, combined into row addresses
    int fl_lo = __ldg(f2lf + l * 64 + lane);
    int fl_hi = __ldg(f2lf + l * 64 + 32 + lane);
    int po_lo = __ldg(f2lp + l * 64 + lane);
    int po_hi = __ldg(f2lp + l * 64 + 32 + lane);
    int ad_lo = (fl_lo * 9 + po_lo) * 32;
    int ad_hi = (fl_hi * 9 + po_hi) * 32;

    float aggd = 0.f;
#pragma unroll 1
    for (int g4 = 0; g4 < 64; g4 += 4) {
        float pgv[4];
#pragma unroll
        for (int u = 0; u < 4; u++) {
            int gi = g4 + u;
            int base = __shfl_sync(0xffffffffu, (gi < 32) ? ad_lo : ad_hi, gi);
            pgv[u] = __ldg(g_pss + base + lane);      // coalesced 128B row
        }
#pragma unroll
        for (int u = 0; u < 4; u++) {
            float pg = pgv[u];
            float a = ab;
#pragma unroll
            for (int k = 0; k < 32; k++)
                a = fmaf(__shfl_sync(0xffffffffu, pg, k), awr[k], a);
            a = (a > 0.f) ? a : 0.2f * a;             // leaky_relu(0.2)
            float e  = __expf(a);                     // |a| small: no max needed
            float se = e;
#pragma unroll
            for (int o = 16; o; o >>= 1) se += __shfl_xor_sync(0xffffffffu, se, o);
            aggd = fmaf(__fdividef(e, se), pg, aggd);
        }
    }

    // ---- link GRU (mh = precomputed MHL) ----
    float az = __ldg(lg_b + lane), ar = __ldg(lg_b + 32 + lane), ah = __ldg(lg_b + 64 + lane);
#pragma unroll
    for (int k = 0; k < 32; k++) {
        float ak = __shfl_sync(0xffffffffu, aggd, k);
        az = fmaf(ak, LW[k * 96 + lane], az);
        ar = fmaf(ak, LW[k * 96 + 32 + lane], ar);
        ah = fmaf(ak, LW[k * 96 + 64 + lane], ah);
    }
    const float* mh = g_MHL + l * 96;
    float hz = mh[lane], hr = mh[32 + lane], hh = mh[64 + lane];
    float h = g_link_state[l * 32 + lane];
    float z  = sig_(az + hz);
    float rr = sig_(ar + hr);
    float c  = tanh_(ah + rr * hh);
    h = z * h + (1.f - z) * c;
    g_link_state[l * 32 + lane] = h;

    // ---- refresh MX / MHL for next iteration ----
    float m0 = __ldg(pg_b + lane), m1 = __ldg(pg_b + 32 + lane), m2 = __ldg(pg_b + 64 + lane);
    float n0 = __ldg(lg_b + 96 + lane), n1 = __ldg(lg_b + 128 + lane), n2 = __ldg(lg_b + 160 + lane);
#pragma unroll
    for (int k = 0; k < 32; k++) {
        float hk = __shfl_sync(0xffffffffu, h, k);
        m0 = fmaf(hk, PW[k * 96 + lane], m0);
        m1 = fmaf(hk, PW[k * 96 + 32 + lane], m1);
        m2 = fmaf(hk, PW[k * 96 + 64 + lane], m2);
        n0 = fmaf(hk, LU[k * 96 + lane], n0);
        n1 = fmaf(hk, LU[k * 96 + 32 + lane], n1);
        n2 = fmaf(hk, LU[k * 96 + 64 + lane], n2);
    }
    float* mxp = g_MX + l * 96;
    mxp[lane] = m0; mxp[32 + lane] = m1; mxp[64 + lane] = m2;
    float* mhp = g_MHL + l * 96;
    mhp[lane] = n0; mhp[32 + lane] = n1; mhp[64 + lane] = n2;
}

// ---------------- readout (thread per flow) --------------------------------
__global__ __launch_bounds__(128) void readout_kernel(
    const float* __restrict__ pdly, const float* __restrict__ cap,
    const int*   __restrict__ l2f,
    const float* __restrict__ w1, const float* __restrict__ b1,
    const float* __restrict__ w2, const float* __restrict__ b2,
    const float* __restrict__ w3, const float* __restrict__ b3,
    float* __restrict__ out)
{
    __shared__ __align__(16) float W1[512];
    __shared__ __align__(16) float W2[128];
    __shared__ float B1[16], B2[8], W3s[8];
    int tid = threadIdx.x;
    for (int i = tid; i < 512; i += 128) W1[i] = w1[i];
    if (tid < 128) W2[tid] = w2[tid];
    if (tid < 16)  B1[tid] = b1[tid];
    if (tid < 8) { B2[tid] = b2[tid]; W3s[tid] = w3[tid]; }
    __syncthreads();

    int f = blockIdx.x * 128 + tid;
    float b3v = __ldg(b3);
    float acc = 0.f;
#pragma unroll 1
    for (int s = 1; s <= 8; s++) {
        float r[32];
        const float4* row = (const float4*)(g_pss + (f * 9 + s) * 32);
#pragma unroll
        for (int i = 0; i < 8; i++) {
            float4 v = row[i];
            r[4 * i] = v.x; r[4 * i + 1] = v.y; r[4 * i + 2] = v.z; r[4 * i + 3] = v.w;
        }
        float h1[16];
#pragma unroll
        for (int j = 0; j < 16; j++) h1[j] = B1[j];
#pragma unroll
        for (int k = 0; k < 32; k++) {
            float rk = r[k];
            const float4* wr = (const float4*)(W1 + k * 16);
#pragma unroll
            for (int q = 0; q < 4; q++) {
                float4 wv = wr[q];
                h1[4 * q]     += rk * wv.x;
                h1[4 * q + 1] += rk * wv.y;
                h1[4 * q + 2] += rk * wv.z;
                h1[4 * q + 3] += rk * wv.w;
            }
        }
#pragma unroll
        for (int j = 0; j < 16; j++) h1[j] = selu_(h1[j]);
        float h2[8];
#pragma unroll
        for (int j = 0; j < 8; j++) h2[j] = B2[j];
#pragma unroll
        for (int k = 0; k < 16; k++) {
            float rk = h1[k];
            const float4* wr = (const float4*)(W2 + k * 8);
            float4 wa = wr[0], wb = wr[1];
            h2[0] += rk * wa.x; h2[1] += rk * wa.y; h2[2] += rk * wa.z; h2[3] += rk * wa.w;
            h2[4] += rk * wb.x; h2[5] += rk * wb.y; h2[6] += rk * wb.z; h2[7] += rk * wb.w;
        }
        float a = b3v;
#pragma unroll
        for (int k = 0; k < 8; k++) a += selu_(h2[k]) * W3s[k];
        int lidx = __ldg(l2f + f * 8 + (s - 1));
        acc += __fdividef(softplus_(a), __ldg(cap + lidx));
    }
    out[f] = acc + pdly[f];
}

// ---------------- launch ----------------------------------------------------
extern "C" void kernel_launch(void* const* d_in, const int* in_sizes, int n_in,
                              void* d_out, int out_size)
{
    (void)in_sizes; (void)n_in; (void)out_size;
    const float* tr    = (const float*)d_in[0];
    const float* ln    = (const float*)d_in[1];
    const float* lo    = (const float*)d_in[2];
    const float* pdly  = (const float*)d_in[3];
    /* d_in[4] flow_packet_size unused by reference */
    const float* cap   = (const float*)d_in[5];
    const int*   l2f   = (const int*)d_in[6];
    const int*   f2lf  = (const int*)d_in[7];
    const int*   f2lp  = (const int*)d_in[8];
    const float* fe_w1 = (const float*)d_in[9];
    const float* fe_b1 = (const float*)d_in[10];
    const float* fe_w2 = (const float*)d_in[11];
    const float* fe_b2 = (const float*)d_in[12];
    const float* le_w1 = (const float*)d_in[13];
    const float* le_b1 = (const float*)d_in[14];
    const float* le_w2 = (const float*)d_in[15];
    const float* le_b2 = (const float*)d_in[16];
    const float* att_w = (const float*)d_in[17];
    const float* att_b = (const float*)d_in[18];
    const float* pg_w  = (const float*)d_in[19];
    const float* pg_u  = (const float*)d_in[20];
    const float* pg_b  = (const float*)d_in[21];
    const float* lg_w  = (const float*)d_in[22];
    const float* lg_u  = (const float*)d_in[23];
    const float* lg_b  = (const float*)d_in[24];
    const float* ro_w1 = (const float*)d_in[25];
    const float* ro_b1 = (const float*)d_in[26];
    const float* ro_w2 = (const float*)d_in[27];
    const float* ro_b2 = (const float*)d_in[28];
    const float* ro_w3 = (const float*)d_in[29];
    const float* ro_b3 = (const float*)d_in[30];
    float* out = (float*)d_out;

    flow_init_kernel<<<F_N / 8, 256>>>(tr, ln, lo, pdly, fe_w1, fe_b1, fe_w2, fe_b2);
    link_init_kernel<<<NL_N / 8, 256>>>(tr, cap, f2lf, le_w1, le_b1, le_w2, le_b2,
                                        pg_w, pg_b, lg_u, lg_b);
    for (int it = 0; it < IT_N; ++it) {
        path_kernel<<<296, 256>>>(l2f, pg_u, pg_b);
        link_kernel<<<NL_N / 8, 256>>>(f2lf, f2lp, att_w, att_b,
                                       lg_w, lg_b, pg_w, pg_b, lg_u);
    }
    readout_kernel<<<F_N / 128, 128>>>(pdly, cap, l2f,
                                       ro_w1, ro_b1, ro_w2, ro_b2, ro_w3, ro_b3, out);
}

// round 5
// speedup vs baseline: 3.4507x; 1.0659x over previous
#include <cuda_runtime.h>

#define F_N   65536
#define LP_N  8
#define NL_N  8192
#define DG_N  64
#define D_N   32
#define IT_N  8

// ---------------- scratch (static device globals; no allocation) -----------
__device__ float g_path_state[F_N * D_N];        //   8 MB
__device__ float g_link_state[NL_N * D_N];       //   1 MB
// per (flow, pos) row: 32 x float2 {h_j, score_j}  (score = precomputed softmax)
__device__ float g_pss[F_N * 9 * 64];            // 151 MB  [F][9][64]
__device__ float g_MX [NL_N * 96];               //   3 MB  link_state @ pg_w + pg_b[0]
__device__ float g_MHL[NL_N * 96];               //   3 MB  link_state @ lg_u + lg_b[1]

// ---------------- helpers ---------------------------------------------------
__device__ __forceinline__ float sig_(float x)  { return __fdividef(1.f, 1.f + __expf(-x)); }
__device__ __forceinline__ float tanh_(float x) { return __fdividef(2.f, 1.f + __expf(-2.f * x)) - 1.f; }
__device__ __forceinline__ float selu_(float x) {
    return x > 0.f ? 1.0507009873554805f * x
                   : 1.7580993408473766f * (__expf(x) - 1.f);
}
__device__ __forceinline__ float softplus_(float x) {
    if (x > 15.f) return x;
    return __logf(1.f + __expf(x));
}
// f32x2 packed math (sm_10x)
__device__ __forceinline__ unsigned long long pk2_(float lo, float hi) {
    unsigned long long r;
    asm("mov.b64 %0, {%1, %2};" : "=l"(r) : "f"(lo), "f"(hi));
    return r;
}
__device__ __forceinline__ void up2_(float& lo, float& hi, unsigned long long v) {
    asm("mov.b64 {%0, %1}, %2;" : "=f"(lo), "=f"(hi) : "l"(v));
}
__device__ __forceinline__ void fma2_(unsigned long long& d, unsigned long long a,
                                      unsigned long long b, unsigned long long c) {
    asm("fma.rn.f32x2 %0, %1, %2, %3;" : "=l"(d) : "l"(a), "l"(b), "l"(c));
}

// ---------------- init: flow encoder (warp per flow) -----------------------
__global__ __launch_bounds__(256) void flow_init_kernel(
    const float* __restrict__ tr, const float* __restrict__ ln,
    const float* __restrict__ lo, const float* __restrict__ pd,
    const float* __restrict__ w1, const float* __restrict__ b1,
    const float* __restrict__ w2, const float* __restrict__ b2)
{
    int lane = threadIdx.x & 31;
    int f    = (blockIdx.x * 256 + threadIdx.x) >> 5;
    float x0 = (tr[f] - 0.5f) * 2.f;
    float x1 = (ln[f] - 0.5f) * 2.f;
    float x2 = (lo[f] - 0.1f) * 5.f;
    float x3 = (pd[f] - 0.2f) * 3.f;
    float h1 = b1[lane] + x0 * w1[lane] + x1 * w1[32 + lane]
                        + x2 * w1[64 + lane] + x3 * w1[96 + lane];
    h1 = selu_(h1);
    float o = b2[lane];
#pragma unroll
    for (int k = 0; k < 32; k++)
        o += __shfl_sync(0xffffffffu, h1, k) * w2[k * 32 + lane];
    g_path_state[f * 32 + lane] = selu_(o);
}

// ---------------- init: link encoder + MX/MHL (warp per link) --------------
__global__ __launch_bounds__(256) void link_init_kernel(
    const float* __restrict__ tr, const float* __restrict__ cap,
    const int*   __restrict__ f2lf,
    const float* __restrict__ w1, const float* __restrict__ b1,
    const float* __restrict__ w2, const float* __restrict__ b2,
    const float* __restrict__ pg_w, const float* __restrict__ pg_b,
    const float* __restrict__ lg_u, const float* __restrict__ lg_b)
{
    int lane = threadIdx.x & 31;
    int l    = (blockIdx.x * 256 + threadIdx.x) >> 5;
    float s = tr[f2lf[l * 64 + lane]] + tr[f2lf[l * 64 + 32 + lane]];
#pragma unroll
    for (int o = 16; o; o >>= 1) s += __shfl_xor_sync(0xffffffffu, s, o);
    float c    = cap[l];
    float load = __fdividef(s * (1.f / 64.f), c);
    float x0 = (c - 1.f);
    float h1 = selu_(b1[lane] + x0 * w1[lane] + load * w1[32 + lane]);
    float o2 = b2[lane];
#pragma unroll
    for (int k = 0; k < 32; k++)
        o2 += __shfl_sync(0xffffffffu, h1, k) * w2[k * 32 + lane];
    float ls = selu_(o2);
    g_link_state[l * 32 + lane] = ls;

    float m0 = pg_b[lane], m1 = pg_b[32 + lane], m2 = pg_b[64 + lane];
    float n0 = lg_b[96 + lane], n1 = lg_b[128 + lane], n2 = lg_b[160 + lane];
#pragma unroll
    for (int k = 0; k < 32; k++) {
        float hk = __shfl_sync(0xffffffffu, ls, k);
        m0 += hk * pg_w[k * 96 + lane];
        m1 += hk * pg_w[k * 96 + 32 + lane];
        m2 += hk * pg_w[k * 96 + 64 + lane];
        n0 += hk * lg_u[k * 96 + lane];
        n1 += hk * lg_u[k * 96 + 32 + lane];
        n2 += hk * lg_u[k * 96 + 64 + lane];
    }
    g_MX [l * 96 + lane] = m0; g_MX [l * 96 + 32 + lane] = m1; g_MX [l * 96 + 64 + lane] = m2;
    g_MHL[l * 96 + lane] = n0; g_MHL[l * 96 + 32 + lane] = n1; g_MHL[l * 96 + 64 + lane] = n2;
}

// ---------------- path GRU scan + fused attention-softmax ------------------
// warp per flow (grid-stride). pg_u columns + att_w column in registers,
// packed as f32x2 pairs: (uz,ur) and (uh,aw). Attention score rides the same
// h-broadcast shuffles as the GRU recurrence; softmax over channels done here
// so link_kernel needs zero shuffles.
__global__ __launch_bounds__(128) void path_kernel(
    const int* __restrict__ l2f,
    const float* __restrict__ pg_u, const float* __restrict__ pg_b,
    const float* __restrict__ att_w, const float* __restrict__ att_b)
{
    int lane = threadIdx.x & 31;
    unsigned long long uzr[32], uha[32];
#pragma unroll
    for (int k = 0; k < 32; k++) {
        uzr[k] = pk2_(__ldg(pg_u + k * 96 + lane), __ldg(pg_u + k * 96 + 32 + lane));
        uha[k] = pk2_(__ldg(pg_u + k * 96 + 64 + lane), __ldg(att_w + k * 32 + lane));
    }
    float bz = __ldg(pg_b + 96 + lane);
    float br = __ldg(pg_b + 128 + lane);
    float bh = __ldg(pg_b + 160 + lane);
    float ab = __ldg(att_b + lane);
    unsigned long long bzr = pk2_(bz, br), bha = pk2_(bh, ab);

    int warps_total = gridDim.x * (blockDim.x >> 5);
    int wid = blockIdx.x * (blockDim.x >> 5) + (threadIdx.x >> 5);

    for (int f = wid; f < F_N; f += warps_total) {
        float h = g_path_state[f * 32 + lane];
        float2* pssf = (float2*)(g_pss + f * 576);
        const int* lrow = l2f + f * 8;

        int l = __ldg(lrow);
        const float* mx = g_MX + l * 96;
        float xz = __ldg(mx + lane), xr = __ldg(mx + 32 + lane), xh = __ldg(mx + 64 + lane);

#pragma unroll 1
        for (int s = 0; s < 8; s++) {
            float xzn = 0.f, xrn = 0.f, xhn = 0.f;
            if (s < 7) {                       // prefetch next step's MX row
                int ln2 = __ldg(lrow + s + 1);
                const float* mxn = g_MX + ln2 * 96;
                xzn = __ldg(mxn + lane); xrn = __ldg(mxn + 32 + lane); xhn = __ldg(mxn + 64 + lane);
            }
            unsigned long long azr = bzr, aha = bha;
#pragma unroll
            for (int k = 0; k < 32; k++) {
                float hk = __shfl_sync(0xffffffffu, h, k);
                unsigned long long h2 = pk2_(hk, hk);
                fma2_(azr, h2, uzr[k], azr);
                fma2_(aha, h2, uha[k], aha);
            }
            float az, ar, ah, at;
            up2_(az, ar, azr);
            up2_(ah, at, aha);
            // score of row s (attention softmax over the 32 channels)
            float a  = (at > 0.f) ? at : 0.2f * at;
            float e  = __expf(a);
            float se = e;
#pragma unroll
            for (int o = 16; o; o >>= 1) se += __shfl_xor_sync(0xffffffffu, se, o);
            pssf[s * 32 + lane] = make_float2(h, __fdividef(e, se));
            // GRU update
            float z  = sig_(xz + az);
            float rr = sig_(xr + ar);
            float c  = tanh_(xh + rr * ah);
            h = z * h + (1.f - z) * c;
            xz = xzn; xr = xrn; xh = xhn;
        }
        // final row 8: one extra broadcast pass for its attention score
        {
            float at = ab;
#pragma unroll
            for (int k = 0; k < 32; k++) {
                float hk = __shfl_sync(0xffffffffu, h, k);
                float uh_k, aw_k;
                up2_(uh_k, aw_k, uha[k]);
                at = fmaf(hk, aw_k, at);
            }
            float a  = (at > 0.f) ? at : 0.2f * at;
            float e  = __expf(a);
            float se = e;
#pragma unroll
            for (int o = 16; o; o >>= 1) se += __shfl_xor_sync(0xffffffffu, se, o);
            pssf[8 * 32 + lane] = make_float2(h, __fdividef(e, se));
        }
        g_path_state[f * 32 + lane] = h;
    }
}

// ---------------- link aggregation + GRU: warp per link --------------------
// Attention fully precomputed: per gather pair = one LDG.64 {h,score} + 1 FMA.
__global__ __launch_bounds__(256) void link_kernel(
    const int* __restrict__ f2lf, const int* __restrict__ f2lp,
    const float* __restrict__ lg_w,  const float* __restrict__ lg_b,
    const float* __restrict__ pg_w,  const float* __restrict__ pg_b,
    const float* __restrict__ lg_u)
{
    __shared__ __align__(16) float LW[3072];   // lg_w  [32][96]
    __shared__ __align__(16) float PW[3072];   // pg_w  [32][96]
    __shared__ __align__(16) float LU[3072];   // lg_u  [32][96]
    int tid = threadIdx.x, lane = tid & 31, w = tid >> 5;
    for (int i = tid; i < 3072; i += 256) {
        LW[i] = lg_w[i]; PW[i] = pg_w[i]; LU[i] = lg_u[i];
    }
    __syncthreads();

    int l = blockIdx.x * 8 + w;

    // gather row indices: lane g and g+32
    int fl_lo = __ldg(f2lf + l * 64 + lane);
    int fl_hi = __ldg(f2lf + l * 64 + 32 + lane);
    int po_lo = __ldg(f2lp + l * 64 + lane);
    int po_hi = __ldg(f2lp + l * 64 + 32 + lane);
    int rw_lo = fl_lo * 9 + po_lo;
    int rw_hi = fl_hi * 9 + po_hi;

    const float2* p2 = (const float2*)g_pss;
    float agg = 0.f;
#pragma unroll 1
    for (int g8 = 0; g8 < 64; g8 += 8) {
        float2 v[8];
#pragma unroll
        for (int u = 0; u < 8; u++) {
            int gi  = g8 + u;
            int row = __shfl_sync(0xffffffffu, (gi < 32) ? rw_lo : rw_hi, gi);
            v[u] = __ldg(p2 + row * 32 + lane);        // coalesced 256B row
        }
#pragma unroll
        for (int u = 0; u < 8; u++)
            agg = fmaf(v[u].y, v[u].x, agg);           // score * h
    }

    // ---- link GRU (mh = precomputed MHL) ----
    float az = __ldg(lg_b + lane), ar = __ldg(lg_b + 32 + lane), ah = __ldg(lg_b + 64 + lane);
#pragma unroll
    for (int k = 0; k < 32; k++) {
        float ak = __shfl_sync(0xffffffffu, agg, k);
        az = fmaf(ak, LW[k * 96 + lane], az);
        ar = fmaf(ak, LW[k * 96 + 32 + lane], ar);
        ah = fmaf(ak, LW[k * 96 + 64 + lane], ah);
    }
    const float* mh = g_MHL + l * 96;
    float hz = mh[lane], hr = mh[32 + lane], hh = mh[64 + lane];
    float h = g_link_state[l * 32 + lane];
    float z  = sig_(az + hz);
    float rr = sig_(ar + hr);
    float c  = tanh_(ah + rr * hh);
    h = z * h + (1.f - z) * c;
    g_link_state[l * 32 + lane] = h;

    // ---- refresh MX / MHL for next iteration ----
    float m0 = __ldg(pg_b + lane), m1 = __ldg(pg_b + 32 + lane), m2 = __ldg(pg_b + 64 + lane);
    float n0 = __ldg(lg_b + 96 + lane), n1 = __ldg(lg_b + 128 + lane), n2 = __ldg(lg_b + 160 + lane);
#pragma unroll
    for (int k = 0; k < 32; k++) {
        float hk = __shfl_sync(0xffffffffu, h, k);
        m0 = fmaf(hk, PW[k * 96 + lane], m0);
        m1 = fmaf(hk, PW[k * 96 + 32 + lane], m1);
        m2 = fmaf(hk, PW[k * 96 + 64 + lane], m2);
        n0 = fmaf(hk, LU[k * 96 + lane], n0);
        n1 = fmaf(hk, LU[k * 96 + 32 + lane], n1);
        n2 = fmaf(hk, LU[k * 96 + 64 + lane], n2);
    }
    float* mxp = g_MX + l * 96;
    mxp[lane] = m0; mxp[32 + lane] = m1; mxp[64 + lane] = m2;
    float* mhp = g_MHL + l * 96;
    mhp[lane] = n0; mhp[32 + lane] = n1; mhp[64 + lane] = n2;
}

// ---------------- readout (thread per flow) --------------------------------
__global__ __launch_bounds__(128) void readout_kernel(
    const float* __restrict__ pdly, const float* __restrict__ cap,
    const int*   __restrict__ l2f,
    const float* __restrict__ w1, const float* __restrict__ b1,
    const float* __restrict__ w2, const float* __restrict__ b2,
    const float* __restrict__ w3, const float* __restrict__ b3,
    float* __restrict__ out)
{
    __shared__ __align__(16) float W1[512];
    __shared__ __align__(16) float W2[128];
    __shared__ float B1[16], B2[8], W3s[8];
    int tid = threadIdx.x;
    for (int i = tid; i < 512; i += 128) W1[i] = w1[i];
    if (tid < 128) W2[tid] = w2[tid];
    if (tid < 16)  B1[tid] = b1[tid];
    if (tid < 8) { B2[tid] = b2[tid]; W3s[tid] = w3[tid]; }
    __syncthreads();

    int f = blockIdx.x * 128 + tid;
    float b3v = __ldg(b3);
    float acc = 0.f;
#pragma unroll 1
    for (int s = 1; s <= 8; s++) {
        float r[32];
        const float4* row = (const float4*)(g_pss + f * 576 + s * 64);
#pragma unroll
        for (int i = 0; i < 16; i++) {         // interleaved {h,score}: take x,z
            float4 v = row[i];
            r[2 * i] = v.x; r[2 * i + 1] = v.z;
        }
        float h1[16];
#pragma unroll
        for (int j = 0; j < 16; j++) h1[j] = B1[j];
#pragma unroll
        for (int k = 0; k < 32; k++) {
            float rk = r[k];
            const float4* wr = (const float4*)(W1 + k * 16);
#pragma unroll
            for (int q = 0; q < 4; q++) {
                float4 wv = wr[q];
                h1[4 * q]     += rk * wv.x;
                h1[4 * q + 1] += rk * wv.y;
                h1[4 * q + 2] += rk * wv.z;
                h1[4 * q + 3] += rk * wv.w;
            }
        }
#pragma unroll
        for (int j = 0; j < 16; j++) h1[j] = selu_(h1[j]);
        float h2[8];
#pragma unroll
        for (int j = 0; j < 8; j++) h2[j] = B2[j];
#pragma unroll
        for (int k = 0; k < 16; k++) {
            float rk = h1[k];
            const float4* wr = (const float4*)(W2 + k * 8);
            float4 wa = wr[0], wb = wr[1];
            h2[0] += rk * wa.x; h2[1] += rk * wa.y; h2[2] += rk * wa.z; h2[3] += rk * wa.w;
            h2[4] += rk * wb.x; h2[5] += rk * wb.y; h2[6] += rk * wb.z; h2[7] += rk * wb.w;
        }
        float a = b3v;
#pragma unroll
        for (int k = 0; k < 8; k++) a += selu_(h2[k]) * W3s[k];
        int lidx = __ldg(l2f + f * 8 + (s - 1));
        acc += __fdividef(softplus_(a), __ldg(cap + lidx));
    }
    out[f] = acc + pdly[f];
}

// ---------------- launch ----------------------------------------------------
extern "C" void kernel_launch(void* const* d_in, const int* in_sizes, int n_in,
                              void* d_out, int out_size)
{
    (void)in_sizes; (void)n_in; (void)out_size;
    const float* tr    = (const float*)d_in[0];
    const float* ln    = (const float*)d_in[1];
    const float* lo    = (const float*)d_in[2];
    const float* pdly  = (const float*)d_in[3];
    /* d_in[4] flow_packet_size unused by reference */
    const float* cap   = (const float*)d_in[5];
    const int*   l2f   = (const int*)d_in[6];
    const int*   f2lf  = (const int*)d_in[7];
    const int*   f2lp  = (const int*)d_in[8];
    const float* fe_w1 = (const float*)d_in[9];
    const float* fe_b1 = (const float*)d_in[10];
    const float* fe_w2 = (const float*)d_in[11];
    const float* fe_b2 = (const float*)d_in[12];
    const float* le_w1 = (const float*)d_in[13];
    const float* le_b1 = (const float*)d_in[14];
    const float* le_w2 = (const float*)d_in[15];
    const float* le_b2 = (const float*)d_in[16];
    const float* att_w = (const float*)d_in[17];
    const float* att_b = (const float*)d_in[18];
    const float* pg_w  = (const float*)d_in[19];
    const float* pg_u  = (const float*)d_in[20];
    const float* pg_b  = (const float*)d_in[21];
    const float* lg_w  = (const float*)d_in[22];
    const float* lg_u  = (const float*)d_in[23];
    const float* lg_b  = (const float*)d_in[24];
    const float* ro_w1 = (const float*)d_in[25];
    const float* ro_b1 = (const float*)d_in[26];
    const float* ro_w2 = (const float*)d_in[27];
    const float* ro_b2 = (const float*)d_in[28];
    const float* ro_w3 = (const float*)d_in[29];
    const float* ro_b3 = (const float*)d_in[30];
    float* out = (float*)d_out;

    flow_init_kernel<<<F_N / 8, 256>>>(tr, ln, lo, pdly, fe_w1, fe_b1, fe_w2, fe_b2);
    link_init_kernel<<<NL_N / 8, 256>>>(tr, cap, f2lf, le_w1, le_b1, le_w2, le_b2,
                                        pg_w, pg_b, lg_u, lg_b);
    for (int it = 0; it < IT_N; ++it) {
        path_kernel<<<444, 128>>>(l2f, pg_u, pg_b, att_w, att_b);
        link_kernel<<<NL_N / 8, 256>>>(f2lf, f2lp, lg_w, lg_b, pg_w, pg_b, lg_u);
    }
    readout_kernel<<<F_N / 128, 128>>>(pdly, cap, l2f,
                                       ro_w1, ro_b1, ro_w2, ro_b2, ro_w3, ro_b3, out);
}